// round 6
// baseline (speedup 1.0000x reference)
#include <cuda_runtime.h>

#define C_CH   256
#define K_KERN 4
#define HID    64
#define HW     4096
#define B_MAX  32
#define CHUNK_B 16                 // batches per chunk (x-chunk = 67MB < L2)

__device__ float g_gap[B_MAX * C_CH];
__device__ float g_attn[B_MAX * K_KERN];

// ---------------------------------------------------------------------------
// Kernel 1: global average pool per (b,c) plane for one batch-chunk.
// ---------------------------------------------------------------------------
__global__ void __launch_bounds__(256) gap_kernel(const float* __restrict__ x,
                                                  int base_bc) {
    const int bc = base_bc + blockIdx.x;
    const float4* __restrict__ p = (const float4*)(x + (size_t)bc * HW);
    float s = 0.f;
#pragma unroll
    for (int i = 0; i < 4; i++) {
        float4 v = p[threadIdx.x + i * 256];
        s += (v.x + v.y) + (v.z + v.w);
    }
#pragma unroll
    for (int o = 16; o > 0; o >>= 1) s += __shfl_down_sync(0xffffffffu, s, o);
    __shared__ float ws[8];
    const int lane = threadIdx.x & 31, w = threadIdx.x >> 5;
    if (lane == 0) ws[w] = s;
    __syncthreads();
    if (threadIdx.x == 0) {
        float t = 0.f;
#pragma unroll
        for (int i = 0; i < 8; i++) t += ws[i];
        g_gap[bc] = t * (1.0f / (float)HW);
    }
}

// ---------------------------------------------------------------------------
// Kernel 2: fc1 -> relu -> fc2 -> softmax. One block per batch in chunk.
// ---------------------------------------------------------------------------
__global__ void __launch_bounds__(256) attn_kernel(const float* __restrict__ fc1_w,
                                                   const float* __restrict__ fc1_b,
                                                   const float* __restrict__ fc2_w,
                                                   const float* __restrict__ fc2_b,
                                                   int base_b) {
    const int b = base_b + blockIdx.x;
    __shared__ float g[C_CH];
    __shared__ float h[HID];
    __shared__ float lg[K_KERN];

    g[threadIdx.x] = g_gap[b * C_CH + threadIdx.x];
    __syncthreads();

    if (threadIdx.x < HID) {
        const float* __restrict__ wr = fc1_w + threadIdx.x * C_CH;
        float acc = fc1_b[threadIdx.x];
#pragma unroll 8
        for (int c = 0; c < C_CH; c++) acc = fmaf(g[c], wr[c], acc);
        h[threadIdx.x] = fmaxf(acc, 0.f);
    }
    __syncthreads();

    if (threadIdx.x < K_KERN) {
        const float* __restrict__ wr = fc2_w + threadIdx.x * HID;
        float acc = fc2_b[threadIdx.x];
#pragma unroll 8
        for (int j = 0; j < HID; j++) acc = fmaf(h[j], wr[j], acc);
        lg[threadIdx.x] = acc;
    }
    __syncthreads();

    if (threadIdx.x == 0) {
        float m = lg[0];
#pragma unroll
        for (int k = 1; k < K_KERN; k++) m = fmaxf(m, lg[k]);
        float e[K_KERN], s = 0.f;
#pragma unroll
        for (int k = 0; k < K_KERN; k++) { e[k] = expf(lg[k] - m); s += e[k]; }
        const float inv = 1.0f / s;
#pragma unroll
        for (int k = 0; k < K_KERN; k++) g_attn[b * K_KERN + k] = e[k] * inv;
    }
}

// ---------------------------------------------------------------------------
// Kernel 3: depthwise 3x3, effective filter w_eff = sum_k attn[b,k]*w[k,c].
// No smem / no syncthreads. 16 lanes span a 64-wide row (float4/lane),
// horizontal halo via width-16 shuffles; 8-row strip per half-warp with
// 3-row register sliding window. 2 planes per 256-thread block.
// x reads hit L2 (chunk was just streamed by gap); stores are evict-first.
// ---------------------------------------------------------------------------
__device__ __forceinline__ void load_row6(const float4* __restrict__ xp,
                                          int row, int sub, float* d) {
    float4 v;
    if ((unsigned)row < 64u) v = __ldg(&xp[row * 16 + sub]);
    else                     v = make_float4(0.f, 0.f, 0.f, 0.f);
    float l = __shfl_up_sync(0xffffffffu, v.w, 1, 16);
    float r = __shfl_down_sync(0xffffffffu, v.x, 1, 16);
    if (sub == 0)  l = 0.f;
    if (sub == 15) r = 0.f;
    d[0] = l; d[1] = v.x; d[2] = v.y; d[3] = v.z; d[4] = v.w; d[5] = r;
}

__global__ void __launch_bounds__(256) conv_kernel(const float* __restrict__ x,
                                                   const float* __restrict__ conv_w,
                                                   float* __restrict__ out,
                                                   int base_bc) {
    const int tid  = threadIdx.x;
    const int lane = tid & 31;
    const int warp = tid >> 5;
    const int sub  = lane & 15;
    const int gs   = warp * 2 + (lane >> 4);
    const int plane_local = gs >> 3;
    const int strip = gs & 7;

    const int bc = base_bc + blockIdx.x * 2 + plane_local;
    const int b = bc >> 8;
    const int c = bc & 255;

    const float a0 = g_attn[b * 4 + 0];
    const float a1 = g_attn[b * 4 + 1];
    const float a2 = g_attn[b * 4 + 2];
    const float a3 = g_attn[b * 4 + 3];
    float w[9];
    const float* __restrict__ w0 = conv_w + (size_t)0 * C_CH * 9 + c * 9;
    const float* __restrict__ w1 = conv_w + (size_t)1 * C_CH * 9 + c * 9;
    const float* __restrict__ w2 = conv_w + (size_t)2 * C_CH * 9 + c * 9;
    const float* __restrict__ w3 = conv_w + (size_t)3 * C_CH * 9 + c * 9;
#pragma unroll
    for (int i = 0; i < 9; i++)
        w[i] = fmaf(a0, __ldg(&w0[i]),
               fmaf(a1, __ldg(&w1[i]),
               fmaf(a2, __ldg(&w2[i]), a3 * __ldg(&w3[i]))));

    const float4* __restrict__ xp = (const float4*)(x + (size_t)bc * HW);
    float4* __restrict__ op = (float4*)(out + (size_t)bc * HW);

    const int rbase = strip * 8;

    float rb[3][6];
    load_row6(xp, rbase - 1, sub, rb[0]);
    load_row6(xp, rbase,     sub, rb[1]);

#pragma unroll
    for (int rr = 0; rr < 8; rr++) {
        const int i0 = rr % 3;
        const int i1 = (rr + 1) % 3;
        const int i2 = (rr + 2) % 3;
        load_row6(xp, rbase + rr + 1, sub, rb[i2]);

        float4 o;
        float* ov = (float*)&o;
#pragma unroll
        for (int i = 0; i < 4; i++) {
            float acc;
            acc = rb[i0][i]     * w[0];
            acc = fmaf(rb[i0][i + 1], w[1], acc);
            acc = fmaf(rb[i0][i + 2], w[2], acc);
            acc = fmaf(rb[i1][i],     w[3], acc);
            acc = fmaf(rb[i1][i + 1], w[4], acc);
            acc = fmaf(rb[i1][i + 2], w[5], acc);
            acc = fmaf(rb[i2][i],     w[6], acc);
            acc = fmaf(rb[i2][i + 1], w[7], acc);
            acc = fmaf(rb[i2][i + 2], w[8], acc);
            ov[i] = acc;
        }
        __stcs(&op[(rbase + rr) * 16 + sub], o);
    }
}

// ---------------------------------------------------------------------------
extern "C" void kernel_launch(void* const* d_in, const int* in_sizes, int n_in,
                              void* d_out, int out_size) {
    const float* x      = (const float*)d_in[0];
    const float* conv_w = (const float*)d_in[1];
    const float* fc1_w  = (const float*)d_in[2];
    const float* fc1_b  = (const float*)d_in[3];
    const float* fc2_w  = (const float*)d_in[4];
    const float* fc2_b  = (const float*)d_in[5];
    float* out = (float*)d_out;

    const int B = in_sizes[0] / (C_CH * HW);   // 32

    for (int cb = 0; cb < B; cb += CHUNK_B) {
        const int nb = (B - cb) < CHUNK_B ? (B - cb) : CHUNK_B;
        const int base_bc = cb * C_CH;
        gap_kernel<<<nb * C_CH, 256>>>(x, base_bc);
        attn_kernel<<<nb, 256>>>(fc1_w, fc1_b, fc2_w, fc2_b, cb);
        conv_kernel<<<nb * C_CH / 2, 256>>>(x, conv_w, out, base_bc);
    }
}

// round 9
// speedup vs baseline: 1.2816x; 1.2816x over previous
#include <cuda_runtime.h>

#define C_CH   256
#define K_KERN 4
#define HID    64
#define HW     4096
#define B_MAX  32

__device__ float g_gap[B_MAX * C_CH];
__device__ float g_attn[B_MAX * K_KERN];

// ---------------------------------------------------------------------------
// L2 eviction-priority helpers (createpolicy + cache_hint form: legal for
// .v4.f32 on sm_103a, unlike the bare .L2::evict_* qualifier)
// ---------------------------------------------------------------------------
__device__ __forceinline__ unsigned long long mk_policy_evict_last() {
    unsigned long long pol;
    asm("createpolicy.fractional.L2::evict_last.b64 %0, 1.0;" : "=l"(pol));
    return pol;
}
__device__ __forceinline__ unsigned long long mk_policy_evict_first() {
    unsigned long long pol;
    asm("createpolicy.fractional.L2::evict_first.b64 %0, 1.0;" : "=l"(pol));
    return pol;
}
__device__ __forceinline__ float4 ld_f4_hint(const float4* p, unsigned long long pol) {
    float4 v;
    asm volatile("ld.global.nc.L2::cache_hint.v4.f32 {%0,%1,%2,%3}, [%4], %5;"
                 : "=f"(v.x), "=f"(v.y), "=f"(v.z), "=f"(v.w)
                 : "l"(p), "l"(pol));
    return v;
}

// ---------------------------------------------------------------------------
// Kernel 1: global average pool per (b,c) plane. One block per plane.
// Loads x with evict_last policy so x stays L2-resident for conv_kernel.
// ---------------------------------------------------------------------------
__global__ void __launch_bounds__(256) gap_kernel(const float* __restrict__ x) {
    const unsigned long long pol = mk_policy_evict_last();
    const int bc = blockIdx.x;
    const float4* __restrict__ p = (const float4*)(x + (size_t)bc * HW);
    float s = 0.f;
#pragma unroll
    for (int i = 0; i < 4; i++) {
        float4 v = ld_f4_hint(&p[threadIdx.x + i * 256], pol);
        s += (v.x + v.y) + (v.z + v.w);
    }
#pragma unroll
    for (int o = 16; o > 0; o >>= 1) s += __shfl_down_sync(0xffffffffu, s, o);
    __shared__ float ws[8];
    const int lane = threadIdx.x & 31, w = threadIdx.x >> 5;
    if (lane == 0) ws[w] = s;
    __syncthreads();
    if (threadIdx.x == 0) {
        float t = 0.f;
#pragma unroll
        for (int i = 0; i < 8; i++) t += ws[i];
        g_gap[bc] = t * (1.0f / (float)HW);
    }
}

// ---------------------------------------------------------------------------
// Kernel 2: fc1 -> relu -> fc2 -> softmax. One block per batch.
// ---------------------------------------------------------------------------
__global__ void __launch_bounds__(256) attn_kernel(const float* __restrict__ fc1_w,
                                                   const float* __restrict__ fc1_b,
                                                   const float* __restrict__ fc2_w,
                                                   const float* __restrict__ fc2_b) {
    const int b = blockIdx.x;
    __shared__ float g[C_CH];
    __shared__ float h[HID];
    __shared__ float lg[K_KERN];

    g[threadIdx.x] = g_gap[b * C_CH + threadIdx.x];
    __syncthreads();

    if (threadIdx.x < HID) {
        const float* __restrict__ wr = fc1_w + threadIdx.x * C_CH;
        float acc = fc1_b[threadIdx.x];
#pragma unroll 8
        for (int c = 0; c < C_CH; c++) acc = fmaf(g[c], wr[c], acc);
        h[threadIdx.x] = fmaxf(acc, 0.f);
    }
    __syncthreads();

    if (threadIdx.x < K_KERN) {
        const float* __restrict__ wr = fc2_w + threadIdx.x * HID;
        float acc = fc2_b[threadIdx.x];
#pragma unroll 8
        for (int j = 0; j < HID; j++) acc = fmaf(h[j], wr[j], acc);
        lg[threadIdx.x] = acc;
    }
    __syncthreads();

    if (threadIdx.x == 0) {
        float m = lg[0];
#pragma unroll
        for (int k = 1; k < K_KERN; k++) m = fmaxf(m, lg[k]);
        float e[K_KERN], s = 0.f;
#pragma unroll
        for (int k = 0; k < K_KERN; k++) { e[k] = expf(lg[k] - m); s += e[k]; }
        const float inv = 1.0f / s;
#pragma unroll
        for (int k = 0; k < K_KERN; k++) g_attn[b * K_KERN + k] = e[k] * inv;
    }
}

// ---------------------------------------------------------------------------
// Kernel 3: depthwise 3x3, effective filter w_eff = sum_k attn[b,k]*w[k,c].
// No smem / no syncthreads. 16 lanes span a 64-wide row (float4/lane),
// horizontal halo via width-16 shuffles; 8-row strip per half-warp with
// 3-row register sliding window. 2 planes per 256-thread block.
// x reads use evict_first policy (dead after use); stores evict-first.
// Reversed plane order: consume guaranteed-L2-resident tail first.
// ---------------------------------------------------------------------------
__device__ __forceinline__ void load_row6(const float4* __restrict__ xp,
                                          int row, int sub, float* d,
                                          unsigned long long pol) {
    float4 v;
    if ((unsigned)row < 64u) v = ld_f4_hint(&xp[row * 16 + sub], pol);
    else                     v = make_float4(0.f, 0.f, 0.f, 0.f);
    float l = __shfl_up_sync(0xffffffffu, v.w, 1, 16);
    float r = __shfl_down_sync(0xffffffffu, v.x, 1, 16);
    if (sub == 0)  l = 0.f;
    if (sub == 15) r = 0.f;
    d[0] = l; d[1] = v.x; d[2] = v.y; d[3] = v.z; d[4] = v.w; d[5] = r;
}

__global__ void __launch_bounds__(256) conv_kernel(const float* __restrict__ x,
                                                   const float* __restrict__ conv_w,
                                                   float* __restrict__ out) {
    const unsigned long long pol = mk_policy_evict_first();
    const int tid  = threadIdx.x;
    const int lane = tid & 31;
    const int warp = tid >> 5;
    const int sub  = lane & 15;
    const int gs   = warp * 2 + (lane >> 4);
    const int plane_local = gs >> 3;
    const int strip = gs & 7;

    const int pair = gridDim.x - 1 - blockIdx.x;      // reversed order
    const int bc = pair * 2 + plane_local;
    const int b = bc >> 8;
    const int c = bc & 255;

    const float a0 = g_attn[b * 4 + 0];
    const float a1 = g_attn[b * 4 + 1];
    const float a2 = g_attn[b * 4 + 2];
    const float a3 = g_attn[b * 4 + 3];
    float w[9];
    const float* __restrict__ w0 = conv_w + (size_t)0 * C_CH * 9 + c * 9;
    const float* __restrict__ w1 = conv_w + (size_t)1 * C_CH * 9 + c * 9;
    const float* __restrict__ w2 = conv_w + (size_t)2 * C_CH * 9 + c * 9;
    const float* __restrict__ w3 = conv_w + (size_t)3 * C_CH * 9 + c * 9;
#pragma unroll
    for (int i = 0; i < 9; i++)
        w[i] = fmaf(a0, __ldg(&w0[i]),
               fmaf(a1, __ldg(&w1[i]),
               fmaf(a2, __ldg(&w2[i]), a3 * __ldg(&w3[i]))));

    const float4* __restrict__ xp = (const float4*)(x + (size_t)bc * HW);
    float4* __restrict__ op = (float4*)(out + (size_t)bc * HW);

    const int rbase = strip * 8;

    float rb[3][6];
    load_row6(xp, rbase - 1, sub, rb[0], pol);
    load_row6(xp, rbase,     sub, rb[1], pol);

#pragma unroll
    for (int rr = 0; rr < 8; rr++) {
        const int i0 = rr % 3;
        const int i1 = (rr + 1) % 3;
        const int i2 = (rr + 2) % 3;
        load_row6(xp, rbase + rr + 1, sub, rb[i2], pol);

        float4 o;
        float* ov = (float*)&o;
#pragma unroll
        for (int i = 0; i < 4; i++) {
            float acc;
            acc = rb[i0][i]     * w[0];
            acc = fmaf(rb[i0][i + 1], w[1], acc);
            acc = fmaf(rb[i0][i + 2], w[2], acc);
            acc = fmaf(rb[i1][i],     w[3], acc);
            acc = fmaf(rb[i1][i + 1], w[4], acc);
            acc = fmaf(rb[i1][i + 2], w[5], acc);
            acc = fmaf(rb[i2][i],     w[6], acc);
            acc = fmaf(rb[i2][i + 1], w[7], acc);
            acc = fmaf(rb[i2][i + 2], w[8], acc);
            ov[i] = acc;
        }
        __stcs(&op[(rbase + rr) * 16 + sub], o);
    }
}

// ---------------------------------------------------------------------------
extern "C" void kernel_launch(void* const* d_in, const int* in_sizes, int n_in,
                              void* d_out, int out_size) {
    const float* x      = (const float*)d_in[0];
    const float* conv_w = (const float*)d_in[1];
    const float* fc1_w  = (const float*)d_in[2];
    const float* fc1_b  = (const float*)d_in[3];
    const float* fc2_w  = (const float*)d_in[4];
    const float* fc2_b  = (const float*)d_in[5];
    float* out = (float*)d_out;

    const int B = in_sizes[0] / (C_CH * HW);   // 32

    gap_kernel<<<B * C_CH, 256>>>(x);
    attn_kernel<<<B, 256>>>(fc1_w, fc1_b, fc2_w, fc2_b);
    conv_kernel<<<B * C_CH / 2, 256>>>(x, conv_w, out);
}